// round 6
// baseline (speedup 1.0000x reference)
#include <cuda_runtime.h>
#include <math.h>
#include <stdint.h>

// VIN on an 8-CTA cluster with 4-deep ghost zones: each CTA computes a
// trapezoid band (14/12/10/8 rows over 4 sub-iterations) entirely from local
// SMEM, exchanging 4-row halos only every 4 sweeps (2 cluster barriers per
// exchange, 4 exchanges total) instead of per-iteration cross-CTA sync.
// fma.rn.f32x2 computes 2 adjacent cells per thread. Only batch 0 reaches the
// output; the 150-ch hidden conv collapses into a 2-ch 3x3 effective conv;
// the r-part of q (qr) is precomputed once per band row.

#define GH 64
#define GW 64
#define NACT 8
#define NCL 8                  // cluster CTAs
#define RPC 8                  // own rows per CTA
#define GD 4                   // ghost depth
#define BROWS 16               // buffer rows: [rbase-4, rbase+12)
#define QROWS 14               // qr rows: [rbase-3, rbase+11)
#define PW 66                  // padded row stride
#define NTH 448                // 14 warps: one warp per widest-band row
#define NSWEEP 19              // final q uses v after 19 updates

__device__ __forceinline__ uint32_t s2u(const void* p) {
    return (uint32_t)__cvta_generic_to_shared(p);
}
__device__ __forceinline__ uint64_t pack2(float x, float y) {
    uint64_t r;
    asm("mov.b64 %0, {%1, %2};" : "=l"(r) : "f"(x), "f"(y));
    return r;
}
__device__ __forceinline__ float2 unpack2(uint64_t v) {
    float2 f;
    asm("mov.b64 {%0, %1}, %2;" : "=f"(f.x), "=f"(f.y) : "l"(v));
    return f;
}
__device__ __forceinline__ uint64_t fma2(uint64_t a, uint64_t b, uint64_t c) {
    uint64_t d;
    asm("fma.rn.f32x2 %0, %1, %2, %3;" : "=l"(d) : "l"(a), "l"(b), "l"(c));
    return d;
}
__device__ __forceinline__ void cluster_sync() {
    asm volatile("barrier.cluster.arrive.aligned;" ::: "memory");
    asm volatile("barrier.cluster.wait.aligned;" ::: "memory");
}
// two scalar f32 stores into a neighbor CTA's smem (addresses are unaligned-odd)
__device__ __forceinline__ void remote_st2(uint32_t laddr, uint32_t rank,
                                           float v0, float v1) {
    asm volatile(
        "{\n\t.reg .b32 ra;\n\t"
        "mapa.shared::cluster.u32 ra, %0, %1;\n\t"
        "st.shared::cluster.f32 [ra], %2;\n\t"
        "st.shared::cluster.f32 [ra+4], %3;\n\t}"
        :: "r"(laddr), "r"(rank), "f"(v0), "f"(v1) : "memory");
}

__global__ __launch_bounds__(NTH, 1) __cluster_dims__(NCL, 1, 1)
void vin_kernel(const float* __restrict__ X,
                const int* __restrict__ S1,
                const int* __restrict__ S2,
                const float* __restrict__ Wh,
                const float* __restrict__ bh,
                const float* __restrict__ Wr,
                const float* __restrict__ Wq,
                float* __restrict__ out)
{
    __shared__ float rp[BROWS * PW];                 // padded reward band
    __shared__ float vA[BROWS * PW];                 // v ping
    __shared__ float vB[BROWS * PW];                 // v pong
    __shared__ unsigned long long qr2[NACT * NTH];   // packed r-part of q
    __shared__ float wqs[144];                       // raw Wq [8][2][3][3]
    __shared__ float part[19 * 8];                   // weight-collapse partials
    __shared__ float weff[19];                       // eff conv weights + bias

    const int t = threadIdx.x;
    const int rank = blockIdx.x;
    const int rbase = rank * RPC;
    const int li = t >> 5;                           // warp id 0..13
    const int lane = t & 31;
    const int jc = lane * 2;                         // left grid column of pair

    // ---- init: zero buffers (ghosts/padding stay 0), stage weights ----
    for (int i = t; i < BROWS * PW; i += NTH) { rp[i] = 0.f; vA[i] = 0.f; vB[i] = 0.f; }
    for (int i = t; i < NACT * NTH; i += NTH) qr2[i] = 0ull;
    if (t < 144) wqs[t] = Wq[t];
    if (t < 152) {
        int p = t >> 3, c = t & 7;
        float s = 0.f;
        for (int h = c; h < 150; h += 8)
            s += Wr[h] * (p < 18 ? Wh[h * 18 + p] : bh[h]);
        part[p * 8 + c] = s;
    }
    __syncthreads();
    if (t < 19) {
        float s = 0.f;
        #pragma unroll
        for (int c = 0; c < 8; c++) s += part[t * 8 + c];
        weff[t] = s;
    }
    __syncthreads();

    // ---- phase 1: reward over the full 16-row input band ----
    {
        float we[18];
        #pragma unroll
        for (int p = 0; p < 18; p++) we[p] = weff[p];
        const float b0 = weff[18];
        for (int idx = t; idx < BROWS * GW; idx += NTH) {
            int br = idx >> 6, j = idx & 63;
            int g = rbase - GD + br;
            if (g < 0 || g >= GH) continue;          // outside grid -> stays 0
            float acc = b0;
            #pragma unroll
            for (int c = 0; c < 2; c++)
                #pragma unroll
                for (int ky = 0; ky < 3; ky++) {
                    int y = g + ky - 1;
                    if (y < 0 || y >= GH) continue;
                    #pragma unroll
                    for (int kx = 0; kx < 3; kx++) {
                        int x = j + kx - 1;
                        if (x < 0 || x >= GW) continue;
                        acc = fmaf(we[c * 9 + ky * 3 + kx],
                                   X[c * (GH * GW) + y * GW + x], acc);
                    }
                }
            rp[br * PW + j + 1] = acc;
        }
    }
    __syncthreads();

    // ---- phase 2: qr for all 14 band output rows (r-channel of Wq) ----
    {
        // thread (li, lane) owns output row or=li (0..13), grid cols jc, jc+1
        int gq = rbase - (GD - 1) + li;              // global row of this qr row
        if (gq >= 0 && gq < GH) {
            float n[12];                             // rp rows li..li+2, cols jc..jc+3
            #pragma unroll
            for (int ky = 0; ky < 3; ky++)
                #pragma unroll
                for (int kx = 0; kx < 4; kx++)
                    n[ky * 4 + kx] = rp[(li + ky) * PW + jc + kx];
            #pragma unroll
            for (int a = 0; a < NACT; a++) {
                float a0 = 0.f, a1 = 0.f;
                #pragma unroll
                for (int ky = 0; ky < 3; ky++)
                    #pragma unroll
                    for (int kx = 0; kx < 3; kx++) {
                        float wv = wqs[a * 18 + ky * 3 + kx];
                        a0 = fmaf(wv, n[ky * 4 + kx], a0);
                        a1 = fmaf(wv, n[ky * 4 + kx + 1], a1);
                    }
                qr2[a * NTH + li * 32 + lane] = pack2(a0, a1);
            }
        }
    }

    // packed (w,w) v-channel weights, register-resident for the whole loop
    uint64_t wp[NACT * 9];
    #pragma unroll
    for (int a = 0; a < NACT; a++)
        #pragma unroll
        for (int p = 0; p < 9; p++) {
            float wv = wqs[a * 18 + 9 + p];
            wp[a * 9 + p] = pack2(wv, wv);
        }
    __syncthreads();

    // ---- phase 3: 19 sweeps = 4 groups of 4 + 1 group of 3 ----
    float* cur = vA;
    float* nxt = vB;
    for (int gi = 0; gi < 5; gi++) {
        const int steps = (gi == 4) ? 3 : 4;
        for (int s = 0; s < steps; s++) {
            const int nrows = QROWS - 2 * s;         // 14,12,10,8
            const int br = 1 + s + li;               // this warp's buffer row
            const int g = rbase - GD + br;           // global row
            if (li < nrows && g >= 0 && g < GH) {
                uint64_t acc[NACT];
                #pragma unroll
                for (int a = 0; a < NACT; a++)
                    acc[a] = qr2[a * NTH + (br - 1) * 32 + lane];
                #pragma unroll
                for (int ky = 0; ky < 3; ky++) {
                    const float* rowp = cur + (br - 1 + ky) * PW + jc; // 8B aligned
                    uint64_t a01 = *(const uint64_t*)rowp;
                    uint64_t a23 = *(const uint64_t*)(rowp + 2);
                    float2 f01 = unpack2(a01);
                    float2 f23 = unpack2(a23);
                    uint64_t p1 = pack2(f01.y, f23.x);
                    #pragma unroll
                    for (int a = 0; a < NACT; a++) {
                        acc[a] = fma2(wp[a * 9 + ky * 3 + 0], a01, acc[a]);
                        acc[a] = fma2(wp[a * 9 + ky * 3 + 1], p1,  acc[a]);
                        acc[a] = fma2(wp[a * 9 + ky * 3 + 2], a23, acc[a]);
                    }
                }
                float v0 = -INFINITY, v1 = -INFINITY;
                #pragma unroll
                for (int a = 0; a < NACT; a++) {
                    float2 f = unpack2(acc[a]);
                    v0 = fmaxf(v0, f.x);
                    v1 = fmaxf(v1, f.y);
                }
                float* dst = nxt + br * PW + jc + 1;
                dst[0] = v0;
                dst[1] = v1;
            }
            __syncthreads();
            float* tmp = cur; cur = nxt; nxt = tmp;
        }
        // after 4 swaps cur is back to the group-start buffer (vA)
        if (gi < 4) {
            cluster_sync();                          // everyone finished group
            if (li < 8) {                            // warps 0..7 push halos
                const int br = GD + li;              // own rows: buffer 4..11
                float v0 = cur[br * PW + 1 + jc];
                float v1 = cur[br * PW + 2 + jc];
                if (li < 4) {
                    if (rank > 0)                    // rows 4..7 -> upper nbr 12..15
                        remote_st2(s2u(&cur[(12 + li) * PW + 1 + jc]),
                                   rank - 1, v0, v1);
                } else {
                    if (rank < NCL - 1)              // rows 8..11 -> lower nbr 0..3
                        remote_st2(s2u(&cur[(li - 4) * PW + 1 + jc]),
                                   rank + 1, v0, v1);
                }
            }
            cluster_sync();                          // halos visible everywhere
        }
    }

    // ---- phase 4: q at the 64 query points from v19, softmax ----
    if (t < 64) {
        int qi = S1[t], qj = S2[t];
        if (qi >= rbase && qi < rbase + RPC) {       // unique owner CTA
            int br = qi - rbase + GD;                // buffer row 4..11
            float n[9];
            #pragma unroll
            for (int ky = 0; ky < 3; ky++)
                #pragma unroll
                for (int kx = 0; kx < 3; kx++)
                    n[ky * 3 + kx] = cur[(br - 1 + ky) * PW + qj + kx];
            float q[NACT];
            float m = -INFINITY;
            #pragma unroll
            for (int a = 0; a < NACT; a++) {
                float2 qv = unpack2(qr2[a * NTH + (br - 1) * 32 + (qj >> 1)]);
                float acc = (qj & 1) ? qv.y : qv.x;
                #pragma unroll
                for (int p = 0; p < 9; p++)
                    acc = fmaf(wqs[a * 18 + 9 + p], n[p], acc);
                q[a] = acc;
                m = fmaxf(m, acc);
            }
            float s = 0.f;
            #pragma unroll
            for (int a = 0; a < NACT; a++) {
                q[a] = expf(q[a] - m);
                s += q[a];
            }
            float inv = 1.f / s;
            #pragma unroll
            for (int a = 0; a < NACT; a++)
                out[t * NACT + a] = q[a] * inv;
        }
    }
}

extern "C" void kernel_launch(void* const* d_in, const int* in_sizes, int n_in,
                              void* d_out, int out_size)
{
    const float* X  = (const float*)d_in[0];   // [64,2,64,64] (batch 0 only)
    const int*   S1 = (const int*)d_in[1];     // [64]
    const int*   S2 = (const int*)d_in[2];     // [64]
    const float* Wh = (const float*)d_in[3];   // [150,2,3,3]
    const float* bh = (const float*)d_in[4];   // [150]
    const float* Wr = (const float*)d_in[5];   // [1,150,1,1]
    const float* Wq = (const float*)d_in[6];   // [8,2,3,3]
    float* out = (float*)d_out;                // [64,8]

    vin_kernel<<<NCL, NTH>>>(X, S1, S2, Wh, bh, Wr, Wq, out);
}